// round 1
// baseline (speedup 1.0000x reference)
#include <cuda_runtime.h>
#include <cstdint>

// Problem constants (fixed shapes from setup_inputs)
#define BATCH 64
#define HDIM  256
#define WDIM  256
#define HW    (HDIM * WDIM)       // 65536
#define HW4   (HW / 4)            // 16384 float4 groups per channel-plane
#define NK    68                  // keypoints

// Per-batch parameters: M[3][3] (sR with REVERT folded into columns) + t[3]
__device__ float g_P[BATCH][12];

// ---------------------------------------------------------------------------
// Kernel 1: per-batch Umeyama similarity estimate (68 points, 3D)
// One block per batch. Threads 0..67 gather keypoints; parallel float
// reductions; thread 0 does a double-precision Jacobi SVD of A^T A.
// ---------------------------------------------------------------------------
__global__ void umeyama_kernel(const float* __restrict__ Off,
                               const float* __restrict__ Pos,
                               const float* __restrict__ mean,
                               const int* __restrict__ uv)
{
    const int b = blockIdx.x;
    const int t = threadIdx.x;

    __shared__ float s_src[NK][3];
    __shared__ float s_dst[NK][3];
    __shared__ float s_mu[6];     // mu_s[0..2], mu_d[3..5]
    __shared__ float s_A[9];      // A[i][j] = sum dd_i * sd_j   (no /n)
    __shared__ float s_var;       // sum |sd|^2                  (no /n)

    if (t < NK) {
        const int h = uv[2 * t];
        const int w = uv[2 * t + 1];
        const int pix = h * WDIM + w;
        const float rev[3] = {1.0f, -1.0f, 1.0f};
        const size_t base = (size_t)b * 3 * HW;
#pragma unroll
        for (int c = 0; c < 3; c++) {
            float o = Off[base + (size_t)c * HW + pix];
            float m = mean[(size_t)c * HW + pix];
            s_src[t][c] = fmaf(o, 4.0f, m) * rev[c];
            s_dst[t][c] = Pos[base + (size_t)c * HW + pix];
        }
    }
    __syncthreads();

    // 6 independent mean reductions on threads 0..5
    if (t < 6) {
        const int c = t % 3;
        float s = 0.0f;
        if (t < 3) { for (int k = 0; k < NK; k++) s += s_src[k][c]; }
        else       { for (int k = 0; k < NK; k++) s += s_dst[k][c]; }
        s_mu[t] = s / (float)NK;
    }
    __syncthreads();

    // 9 covariance entries + variance on threads 0..9
    if (t < 9) {
        const int i = t / 3, j = t % 3;
        const float mdi = s_mu[3 + i];
        const float msj = s_mu[j];
        float s = 0.0f;
        for (int k = 0; k < NK; k++)
            s += (s_dst[k][i] - mdi) * (s_src[k][j] - msj);
        s_A[t] = s;
    } else if (t == 9) {
        float s = 0.0f;
        for (int k = 0; k < NK; k++) {
#pragma unroll
            for (int c = 0; c < 3; c++) {
                float d = s_src[k][c] - s_mu[c];
                s = fmaf(d, d, s);
            }
        }
        s_var = s;
    }
    __syncthreads();

    if (t != 0) return;

    // ---- double precision closed solve on one thread ----
    double A[3][3];
#pragma unroll
    for (int i = 0; i < 3; i++)
#pragma unroll
        for (int j = 0; j < 3; j++) A[i][j] = (double)s_A[i * 3 + j];

    const double detA =
          A[0][0] * (A[1][1] * A[2][2] - A[1][2] * A[2][1])
        - A[0][1] * (A[1][0] * A[2][2] - A[1][2] * A[2][0])
        + A[0][2] * (A[1][0] * A[2][1] - A[1][1] * A[2][0]);

    // Bm = A^T A  (symmetric PSD)
    double Bm[3][3];
#pragma unroll
    for (int i = 0; i < 3; i++)
#pragma unroll
        for (int j = 0; j < 3; j++) {
            double s = 0.0;
#pragma unroll
            for (int k = 0; k < 3; k++) s += A[k][i] * A[k][j];
            Bm[i][j] = s;
        }

    // Cyclic Jacobi eigen-decomposition of Bm -> V (columns), eigvals on diag
    double V[3][3] = {{1,0,0},{0,1,0},{0,0,1}};
    for (int sweep = 0; sweep < 8; sweep++) {
#pragma unroll
        for (int pq = 0; pq < 3; pq++) {
            const int p = (pq == 2) ? 1 : 0;
            const int q = (pq == 0) ? 1 : 2;
            const double apq = Bm[p][q];
            if (apq == 0.0) continue;
            const double theta = (Bm[q][q] - Bm[p][p]) / (2.0 * apq);
            const double sgn = (theta >= 0.0) ? 1.0 : -1.0;
            const double tt = sgn / (fabs(theta) + sqrt(theta * theta + 1.0));
            const double c  = 1.0 / sqrt(tt * tt + 1.0);
            const double s  = tt * c;
            const double app = Bm[p][p], aqq = Bm[q][q];
            Bm[p][p] = app - tt * apq;
            Bm[q][q] = aqq + tt * apq;
            Bm[p][q] = Bm[q][p] = 0.0;
            const int k = 3 - p - q;
            const double akp = Bm[k][p], akq = Bm[k][q];
            Bm[k][p] = Bm[p][k] = c * akp - s * akq;
            Bm[k][q] = Bm[q][k] = s * akp + c * akq;
#pragma unroll
            for (int r = 0; r < 3; r++) {
                const double vrp = V[r][p], vrq = V[r][q];
                V[r][p] = c * vrp - s * vrq;
                V[r][q] = s * vrp + c * vrq;
            }
        }
    }

    // sort eigenpairs descending
    double wv[3] = {Bm[0][0], Bm[1][1], Bm[2][2]};
    int idx[3] = {0, 1, 2};
#pragma unroll
    for (int i = 0; i < 2; i++)
#pragma unroll
        for (int j = i + 1; j < 3; j++)
            if (wv[idx[j]] > wv[idx[i]]) { int tmp = idx[i]; idx[i] = idx[j]; idx[j] = tmp; }

    double S[3], U[3][3], Vs[3][3];
#pragma unroll
    for (int c2 = 0; c2 < 3; c2++) {
        const int ic = idx[c2];
        const double sv = sqrt(fmax(wv[ic], 0.0));
        S[c2] = sv;
        const double inv = (sv > 0.0) ? 1.0 / sv : 0.0;
#pragma unroll
        for (int r = 0; r < 3; r++) Vs[r][c2] = V[r][ic];
#pragma unroll
        for (int r = 0; r < 3; r++) {
            double s = 0.0;
#pragma unroll
            for (int k = 0; k < 3; k++) s += A[r][k] * Vs[k][c2];
            U[r][c2] = s * inv;
        }
    }

    const double d3 = (detA < 0.0) ? -1.0 : 1.0;
    const double scale = (S[0] + S[1] + d3 * S[2]) / (double)s_var;

    double sR[3][3];
#pragma unroll
    for (int i = 0; i < 3; i++)
#pragma unroll
        for (int j = 0; j < 3; j++) {
            const double r = U[i][0] * Vs[j][0] + U[i][1] * Vs[j][1]
                           + d3 * U[i][2] * Vs[j][2];
            sR[i][j] = scale * r;
        }

    const float rev[3] = {1.0f, -1.0f, 1.0f};
    const double mu_s0 = (double)s_mu[0], mu_s1 = (double)s_mu[1], mu_s2 = (double)s_mu[2];
#pragma unroll
    for (int i = 0; i < 3; i++) {
        const double td = (double)s_mu[3 + i]
                        - (sR[i][0] * mu_s0 + sR[i][1] * mu_s1 + sR[i][2] * mu_s2);
#pragma unroll
        for (int j = 0; j < 3; j++)
            g_P[b][i * 3 + j] = (float)sR[i][j] * rev[j];   // fold REVERT into columns
        g_P[b][9 + i] = (float)td;
    }
}

// ---------------------------------------------------------------------------
// Kernel 2: streaming apply. out[b,d,:] = M[b] @ (4*Off[b,:,:] + mean) + t[b]
// float4 vectorized; mean stays L2-resident across batches.
// ---------------------------------------------------------------------------
__global__ void __launch_bounds__(256)
apply_kernel(const float4* __restrict__ Off,
             const float4* __restrict__ mean,
             float4* __restrict__ out)
{
    const int b = blockIdx.y;
    const int p = blockIdx.x * blockDim.x + threadIdx.x;   // 0..HW4-1

    __shared__ float P[12];
    if (threadIdx.x < 12) P[threadIdx.x] = g_P[b][threadIdx.x];
    __syncthreads();

    const size_t base = (size_t)b * 3 * HW4;
    const float4 x0 = Off[base + p];
    const float4 x1 = Off[base + HW4 + p];
    const float4 x2 = Off[base + 2 * HW4 + p];
    const float4 m0 = mean[p];
    const float4 m1 = mean[HW4 + p];
    const float4 m2 = mean[2 * HW4 + p];

    const float p0 = P[0], p1 = P[1], p2 = P[2];
    const float p3 = P[3], p4 = P[4], p5 = P[5];
    const float p6 = P[6], p7 = P[7], p8 = P[8];
    const float t0 = P[9], t1 = P[10], t2 = P[11];

    float4 y0, y1, y2;
#define DO_LANE(L)                                            \
    {                                                         \
        const float o0 = fmaf(x0.L, 4.0f, m0.L);              \
        const float o1 = fmaf(x1.L, 4.0f, m1.L);              \
        const float o2 = fmaf(x2.L, 4.0f, m2.L);              \
        y0.L = fmaf(p0, o0, fmaf(p1, o1, fmaf(p2, o2, t0)));  \
        y1.L = fmaf(p3, o0, fmaf(p4, o1, fmaf(p5, o2, t1)));  \
        y2.L = fmaf(p6, o0, fmaf(p7, o1, fmaf(p8, o2, t2)));  \
    }
    DO_LANE(x) DO_LANE(y) DO_LANE(z) DO_LANE(w)
#undef DO_LANE

    out[base + p]           = y0;
    out[base + HW4 + p]     = y1;
    out[base + 2 * HW4 + p] = y2;
}

// ---------------------------------------------------------------------------
extern "C" void kernel_launch(void* const* d_in, const int* in_sizes, int n_in,
                              void* d_out, int out_size)
{
    const float* Off  = (const float*)d_in[0];   // [64,3,256,256]
    const float* Pos  = (const float*)d_in[1];   // [64,3,256,256]
    const float* mean = (const float*)d_in[2];   // [3,256,256]
    const int*   uv   = (const int*)d_in[3];     // [68,2] int32

    float* out = (float*)d_out;                  // [64,3,256,256]

    umeyama_kernel<<<BATCH, 96>>>(Off, Pos, mean, uv);

    dim3 grid(HW4 / 256, BATCH);                 // (64, 64)
    apply_kernel<<<grid, 256>>>((const float4*)Off,
                                (const float4*)mean,
                                (float4*)out);
}

// round 2
// speedup vs baseline: 1.2594x; 1.2594x over previous
#include <cuda_runtime.h>
#include <cstdint>

// Problem constants (fixed shapes from setup_inputs)
#define BATCH 64
#define HDIM  256
#define WDIM  256
#define HW    (HDIM * WDIM)       // 65536
#define HW4   (HW / 4)            // 16384 float4 groups per channel-plane
#define NK    68                  // keypoints

// Per-batch parameters: M[3][3] (sR with REVERT folded into columns) + t[3]
__device__ float g_P[BATCH][12];

// ---------------------------------------------------------------------------
// Kernel 1: per-batch Umeyama similarity estimate (68 points, 3D)
// One block per batch. Threads 0..67 gather keypoints; parallel float
// reductions; thread 0 does a fast fp32 Jacobi SVD of A^T A.
// ---------------------------------------------------------------------------
__global__ void umeyama_kernel(const float* __restrict__ Off,
                               const float* __restrict__ Pos,
                               const float* __restrict__ mean,
                               const int* __restrict__ uv)
{
    const int b = blockIdx.x;
    const int t = threadIdx.x;

    __shared__ float s_src[NK][3];
    __shared__ float s_dst[NK][3];
    __shared__ float s_mu[6];     // mu_s[0..2], mu_d[3..5]
    __shared__ float s_A[9];      // A[i][j] = sum dd_i * sd_j   (no /n)
    __shared__ float s_var;       // sum |sd|^2                  (no /n)

    if (t < NK) {
        const int h = uv[2 * t];
        const int w = uv[2 * t + 1];
        const int pix = h * WDIM + w;
        const float rev[3] = {1.0f, -1.0f, 1.0f};
        const size_t base = (size_t)b * 3 * HW;
#pragma unroll
        for (int c = 0; c < 3; c++) {
            float o = Off[base + (size_t)c * HW + pix];
            float m = mean[(size_t)c * HW + pix];
            s_src[t][c] = fmaf(o, 4.0f, m) * rev[c];
            s_dst[t][c] = Pos[base + (size_t)c * HW + pix];
        }
    }
    __syncthreads();

    // 6 independent mean reductions on threads 0..5
    if (t < 6) {
        const int c = t % 3;
        float s = 0.0f;
        if (t < 3) { for (int k = 0; k < NK; k++) s += s_src[k][c]; }
        else       { for (int k = 0; k < NK; k++) s += s_dst[k][c]; }
        s_mu[t] = s / (float)NK;
    }
    __syncthreads();

    // 9 covariance entries + variance on threads 0..9
    if (t < 9) {
        const int i = t / 3, j = t % 3;
        const float mdi = s_mu[3 + i];
        const float msj = s_mu[j];
        float s = 0.0f;
        for (int k = 0; k < NK; k++)
            s += (s_dst[k][i] - mdi) * (s_src[k][j] - msj);
        s_A[t] = s;
    } else if (t == 9) {
        float s = 0.0f;
        for (int k = 0; k < NK; k++) {
#pragma unroll
            for (int c = 0; c < 3; c++) {
                float d = s_src[k][c] - s_mu[c];
                s = fmaf(d, d, s);
            }
        }
        s_var = s;
    }
    __syncthreads();

    if (t != 0) return;

    // ---- fast fp32 closed solve on one thread ----
    float A[3][3];
#pragma unroll
    for (int i = 0; i < 3; i++)
#pragma unroll
        for (int j = 0; j < 3; j++) A[i][j] = s_A[i * 3 + j];

    const float detA =
          A[0][0] * (A[1][1] * A[2][2] - A[1][2] * A[2][1])
        - A[0][1] * (A[1][0] * A[2][2] - A[1][2] * A[2][0])
        + A[0][2] * (A[1][0] * A[2][1] - A[1][1] * A[2][0]);

    // Bm = A^T A  (symmetric PSD)
    float Bm[3][3];
#pragma unroll
    for (int i = 0; i < 3; i++)
#pragma unroll
        for (int j = 0; j < 3; j++) {
            float s = 0.0f;
#pragma unroll
            for (int k = 0; k < 3; k++) s = fmaf(A[k][i], A[k][j], s);
            Bm[i][j] = s;
        }

    // Cyclic Jacobi eigen-decomposition (fp32, exact 2x2 update formulas since
    // the rotation angle is approximate -> compute residual off-diagonal).
    float V[3][3] = {{1,0,0},{0,1,0},{0,0,1}};
    for (int sweep = 0; sweep < 7; sweep++) {
#pragma unroll
        for (int pq = 0; pq < 3; pq++) {
            const int p = (pq == 2) ? 1 : 0;
            const int q = (pq == 0) ? 1 : 2;
            const float apq = Bm[p][q];
            const float app = Bm[p][p], aqq = Bm[q][q];
            if (fabsf(apq) <= 1e-10f * (fabsf(app) + fabsf(aqq))) continue;
            const float theta = __fdividef(aqq - app, 2.0f * apq);
            const float sgn = (theta >= 0.0f) ? 1.0f : -1.0f;
            const float tt = __fdividef(sgn, fabsf(theta) + sqrtf(fmaf(theta, theta, 1.0f)));
            const float c  = rsqrtf(fmaf(tt, tt, 1.0f));
            const float s  = tt * c;
            const float c2 = c * c, s2 = s * s, cs = c * s;
            // exact 2x2 similarity update
            Bm[p][p] = c2 * app - 2.0f * cs * apq + s2 * aqq;
            Bm[q][q] = s2 * app + 2.0f * cs * apq + c2 * aqq;
            const float res = cs * (app - aqq) + (c2 - s2) * apq;
            Bm[p][q] = Bm[q][p] = res;
            const int k = 3 - p - q;
            const float akp = Bm[k][p], akq = Bm[k][q];
            Bm[k][p] = Bm[p][k] = c * akp - s * akq;
            Bm[k][q] = Bm[q][k] = s * akp + c * akq;
#pragma unroll
            for (int r = 0; r < 3; r++) {
                const float vrp = V[r][p], vrq = V[r][q];
                V[r][p] = c * vrp - s * vrq;
                V[r][q] = s * vrp + c * vrq;
            }
        }
    }

    // sort eigenpairs descending
    float wv[3] = {Bm[0][0], Bm[1][1], Bm[2][2]};
    int idx[3] = {0, 1, 2};
#pragma unroll
    for (int i = 0; i < 2; i++)
#pragma unroll
        for (int j = i + 1; j < 3; j++)
            if (wv[idx[j]] > wv[idx[i]]) { int tmp = idx[i]; idx[i] = idx[j]; idx[j] = tmp; }

    float S[3], U[3][3], Vs[3][3];
#pragma unroll
    for (int c2 = 0; c2 < 3; c2++) {
        const int ic = idx[c2];
        const float sv = sqrtf(fmaxf(wv[ic], 0.0f));
        S[c2] = sv;
        const float inv = (sv > 0.0f) ? __fdividef(1.0f, sv) : 0.0f;
#pragma unroll
        for (int r = 0; r < 3; r++) Vs[r][c2] = V[r][ic];
#pragma unroll
        for (int r = 0; r < 3; r++) {
            float s = 0.0f;
#pragma unroll
            for (int k = 0; k < 3; k++) s = fmaf(A[r][k], Vs[k][c2], s);
            U[r][c2] = s * inv;
        }
    }

    const float d3 = (detA < 0.0f) ? -1.0f : 1.0f;
    const float scale = __fdividef(S[0] + S[1] + d3 * S[2], s_var);

    float sR[3][3];
#pragma unroll
    for (int i = 0; i < 3; i++)
#pragma unroll
        for (int j = 0; j < 3; j++) {
            const float r = U[i][0] * Vs[j][0] + U[i][1] * Vs[j][1]
                          + d3 * U[i][2] * Vs[j][2];
            sR[i][j] = scale * r;
        }

    const float rev[3] = {1.0f, -1.0f, 1.0f};
    const float mu_s0 = s_mu[0], mu_s1 = s_mu[1], mu_s2 = s_mu[2];
#pragma unroll
    for (int i = 0; i < 3; i++) {
        const float td = s_mu[3 + i]
                       - (sR[i][0] * mu_s0 + sR[i][1] * mu_s1 + sR[i][2] * mu_s2);
#pragma unroll
        for (int j = 0; j < 3; j++)
            g_P[b][i * 3 + j] = sR[i][j] * rev[j];   // fold REVERT into columns
        g_P[b][9 + i] = td;
    }
}

// ---------------------------------------------------------------------------
// Kernel 2: streaming apply. out[b,d,:] = M[b] @ (4*Off[b,:,:] + mean) + t[b]
// float4 vectorized, 2 pixel-quads per thread for deeper MLP.
// Off: read-once -> __ldcs (evict-first). mean: reused 64x -> __ldg.
// ---------------------------------------------------------------------------
#define TPB 256
#define VEC 2

__global__ void __launch_bounds__(TPB)
apply_kernel(const float4* __restrict__ Off,
             const float4* __restrict__ mean,
             float4* __restrict__ out)
{
    const int b = blockIdx.y;
    const int p0 = blockIdx.x * (TPB * VEC) + threadIdx.x;

    __shared__ float P[12];
    if (threadIdx.x < 12) P[threadIdx.x] = g_P[b][threadIdx.x];
    __syncthreads();

    const size_t base = (size_t)b * 3 * HW4;

    // issue all 12 loads up front (6 per pixel-quad)
    float4 x0a = __ldcs(&Off[base + p0]);
    float4 x1a = __ldcs(&Off[base + HW4 + p0]);
    float4 x2a = __ldcs(&Off[base + 2 * HW4 + p0]);
    float4 x0b = __ldcs(&Off[base + p0 + TPB]);
    float4 x1b = __ldcs(&Off[base + HW4 + p0 + TPB]);
    float4 x2b = __ldcs(&Off[base + 2 * HW4 + p0 + TPB]);
    float4 m0a = __ldg(&mean[p0]);
    float4 m1a = __ldg(&mean[HW4 + p0]);
    float4 m2a = __ldg(&mean[2 * HW4 + p0]);
    float4 m0b = __ldg(&mean[p0 + TPB]);
    float4 m1b = __ldg(&mean[HW4 + p0 + TPB]);
    float4 m2b = __ldg(&mean[2 * HW4 + p0 + TPB]);

    const float q0 = P[0], q1 = P[1], q2 = P[2];
    const float q3 = P[3], q4 = P[4], q5 = P[5];
    const float q6 = P[6], q7 = P[7], q8 = P[8];
    const float t0 = P[9], t1 = P[10], t2 = P[11];

#define DO_LANE(x0, x1, x2, m0, m1, m2, y0, y1, y2, L)        \
    {                                                         \
        const float o0 = fmaf(x0.L, 4.0f, m0.L);              \
        const float o1 = fmaf(x1.L, 4.0f, m1.L);              \
        const float o2 = fmaf(x2.L, 4.0f, m2.L);              \
        y0.L = fmaf(q0, o0, fmaf(q1, o1, fmaf(q2, o2, t0)));  \
        y1.L = fmaf(q3, o0, fmaf(q4, o1, fmaf(q5, o2, t1)));  \
        y2.L = fmaf(q6, o0, fmaf(q7, o1, fmaf(q8, o2, t2)));  \
    }

    float4 y0a, y1a, y2a;
    DO_LANE(x0a, x1a, x2a, m0a, m1a, m2a, y0a, y1a, y2a, x)
    DO_LANE(x0a, x1a, x2a, m0a, m1a, m2a, y0a, y1a, y2a, y)
    DO_LANE(x0a, x1a, x2a, m0a, m1a, m2a, y0a, y1a, y2a, z)
    DO_LANE(x0a, x1a, x2a, m0a, m1a, m2a, y0a, y1a, y2a, w)
    out[base + p0]           = y0a;
    out[base + HW4 + p0]     = y1a;
    out[base + 2 * HW4 + p0] = y2a;

    float4 y0b, y1b, y2b;
    DO_LANE(x0b, x1b, x2b, m0b, m1b, m2b, y0b, y1b, y2b, x)
    DO_LANE(x0b, x1b, x2b, m0b, m1b, m2b, y0b, y1b, y2b, y)
    DO_LANE(x0b, x1b, x2b, m0b, m1b, m2b, y0b, y1b, y2b, z)
    DO_LANE(x0b, x1b, x2b, m0b, m1b, m2b, y0b, y1b, y2b, w)
    out[base + p0 + TPB]           = y0b;
    out[base + HW4 + p0 + TPB]     = y1b;
    out[base + 2 * HW4 + p0 + TPB] = y2b;
#undef DO_LANE
}

// ---------------------------------------------------------------------------
extern "C" void kernel_launch(void* const* d_in, const int* in_sizes, int n_in,
                              void* d_out, int out_size)
{
    const float* Off  = (const float*)d_in[0];   // [64,3,256,256]
    const float* Pos  = (const float*)d_in[1];   // [64,3,256,256]
    const float* mean = (const float*)d_in[2];   // [3,256,256]
    const int*   uv   = (const int*)d_in[3];     // [68,2] int32

    float* out = (float*)d_out;                  // [64,3,256,256]

    umeyama_kernel<<<BATCH, 96>>>(Off, Pos, mean, uv);

    dim3 grid(HW4 / (TPB * VEC), BATCH);         // (32, 64)
    apply_kernel<<<grid, TPB>>>((const float4*)Off,
                                (const float4*)mean,
                                (float4*)out);
}

// round 4
// speedup vs baseline: 1.3579x; 1.0782x over previous
#include <cuda_runtime.h>
#include <cstdint>

// Problem constants (fixed shapes from setup_inputs)
#define BATCH 64
#define HDIM  256
#define WDIM  256
#define HW    (HDIM * WDIM)       // 65536
#define HW4   (HW / 4)            // 16384 float4 groups per channel-plane
#define NK    68                  // keypoints

// Per-batch parameters: M[3][3] (sR with REVERT folded into columns) + t[3]
__device__ float g_P[BATCH][12];

// ---------------------------------------------------------------------------
// Kernel 1: per-batch Umeyama similarity estimate (68 points, 3D)
// ---------------------------------------------------------------------------
__global__ void umeyama_kernel(const float* __restrict__ Off,
                               const float* __restrict__ Pos,
                               const float* __restrict__ mean,
                               const int* __restrict__ uv)
{
    const int b = blockIdx.x;
    const int t = threadIdx.x;

    __shared__ float s_src[NK][3];
    __shared__ float s_dst[NK][3];
    __shared__ float s_mu[6];     // mu_s[0..2], mu_d[3..5]
    __shared__ float s_A[9];      // A[i][j] = sum dd_i * sd_j   (no /n)
    __shared__ float s_var;       // sum |sd|^2                  (no /n)

    if (t < NK) {
        const int h = uv[2 * t];
        const int w = uv[2 * t + 1];
        const int pix = h * WDIM + w;
        const float rev[3] = {1.0f, -1.0f, 1.0f};
        const size_t base = (size_t)b * 3 * HW;
#pragma unroll
        for (int c = 0; c < 3; c++) {
            float o = Off[base + (size_t)c * HW + pix];
            float m = mean[(size_t)c * HW + pix];
            s_src[t][c] = fmaf(o, 4.0f, m) * rev[c];
            s_dst[t][c] = Pos[base + (size_t)c * HW + pix];
        }
    }
    __syncthreads();

    if (t < 6) {
        const int c = t % 3;
        float s = 0.0f;
        if (t < 3) { for (int k = 0; k < NK; k++) s += s_src[k][c]; }
        else       { for (int k = 0; k < NK; k++) s += s_dst[k][c]; }
        s_mu[t] = s / (float)NK;
    }
    __syncthreads();

    if (t < 9) {
        const int i = t / 3, j = t % 3;
        const float mdi = s_mu[3 + i];
        const float msj = s_mu[j];
        float s = 0.0f;
        for (int k = 0; k < NK; k++)
            s += (s_dst[k][i] - mdi) * (s_src[k][j] - msj);
        s_A[t] = s;
    } else if (t == 9) {
        float s = 0.0f;
        for (int k = 0; k < NK; k++) {
#pragma unroll
            for (int c = 0; c < 3; c++) {
                float d = s_src[k][c] - s_mu[c];
                s = fmaf(d, d, s);
            }
        }
        s_var = s;
    }
    __syncthreads();

    if (t != 0) return;

    // ---- fast fp32 closed solve on one thread ----
    float A[3][3];
#pragma unroll
    for (int i = 0; i < 3; i++)
#pragma unroll
        for (int j = 0; j < 3; j++) A[i][j] = s_A[i * 3 + j];

    const float detA =
          A[0][0] * (A[1][1] * A[2][2] - A[1][2] * A[2][1])
        - A[0][1] * (A[1][0] * A[2][2] - A[1][2] * A[2][0])
        + A[0][2] * (A[1][0] * A[2][1] - A[1][1] * A[2][0]);

    float Bm[3][3];
#pragma unroll
    for (int i = 0; i < 3; i++)
#pragma unroll
        for (int j = 0; j < 3; j++) {
            float s = 0.0f;
#pragma unroll
            for (int k = 0; k < 3; k++) s = fmaf(A[k][i], A[k][j], s);
            Bm[i][j] = s;
        }

    // Cyclic Jacobi (fp32, exact 2x2 update w/ residual off-diagonal)
    float V[3][3] = {{1,0,0},{0,1,0},{0,0,1}};
    for (int sweep = 0; sweep < 5; sweep++) {
#pragma unroll
        for (int pq = 0; pq < 3; pq++) {
            const int p = (pq == 2) ? 1 : 0;
            const int q = (pq == 0) ? 1 : 2;
            const float apq = Bm[p][q];
            const float app = Bm[p][p], aqq = Bm[q][q];
            if (fabsf(apq) <= 1e-10f * (fabsf(app) + fabsf(aqq))) continue;
            const float theta = __fdividef(aqq - app, 2.0f * apq);
            const float sgn = (theta >= 0.0f) ? 1.0f : -1.0f;
            const float tt = __fdividef(sgn, fabsf(theta) + sqrtf(fmaf(theta, theta, 1.0f)));
            const float c  = rsqrtf(fmaf(tt, tt, 1.0f));
            const float s  = tt * c;
            const float c2 = c * c, s2 = s * s, cs = c * s;
            Bm[p][p] = c2 * app - 2.0f * cs * apq + s2 * aqq;
            Bm[q][q] = s2 * app + 2.0f * cs * apq + c2 * aqq;
            const float res = cs * (app - aqq) + (c2 - s2) * apq;
            Bm[p][q] = Bm[q][p] = res;
            const int k = 3 - p - q;
            const float akp = Bm[k][p], akq = Bm[k][q];
            Bm[k][p] = Bm[p][k] = c * akp - s * akq;
            Bm[k][q] = Bm[q][k] = s * akp + c * akq;
#pragma unroll
            for (int r = 0; r < 3; r++) {
                const float vrp = V[r][p], vrq = V[r][q];
                V[r][p] = c * vrp - s * vrq;
                V[r][q] = s * vrp + c * vrq;
            }
        }
    }

    float wv[3] = {Bm[0][0], Bm[1][1], Bm[2][2]};
    int idx[3] = {0, 1, 2};
#pragma unroll
    for (int i = 0; i < 2; i++)
#pragma unroll
        for (int j = i + 1; j < 3; j++)
            if (wv[idx[j]] > wv[idx[i]]) { int tmp = idx[i]; idx[i] = idx[j]; idx[j] = tmp; }

    float S[3], U[3][3], Vs[3][3];
#pragma unroll
    for (int c2 = 0; c2 < 3; c2++) {
        const int ic = idx[c2];
        const float sv = sqrtf(fmaxf(wv[ic], 0.0f));
        S[c2] = sv;
        const float inv = (sv > 0.0f) ? __fdividef(1.0f, sv) : 0.0f;
#pragma unroll
        for (int r = 0; r < 3; r++) Vs[r][c2] = V[r][ic];
#pragma unroll
        for (int r = 0; r < 3; r++) {
            float s = 0.0f;
#pragma unroll
            for (int k = 0; k < 3; k++) s = fmaf(A[r][k], Vs[k][c2], s);
            U[r][c2] = s * inv;
        }
    }

    const float d3 = (detA < 0.0f) ? -1.0f : 1.0f;
    const float scale = __fdividef(S[0] + S[1] + d3 * S[2], s_var);

    float sR[3][3];
#pragma unroll
    for (int i = 0; i < 3; i++)
#pragma unroll
        for (int j = 0; j < 3; j++) {
            const float r = U[i][0] * Vs[j][0] + U[i][1] * Vs[j][1]
                          + d3 * U[i][2] * Vs[j][2];
            sR[i][j] = scale * r;
        }

    const float rev[3] = {1.0f, -1.0f, 1.0f};
    const float mu_s0 = s_mu[0], mu_s1 = s_mu[1], mu_s2 = s_mu[2];
#pragma unroll
    for (int i = 0; i < 3; i++) {
        const float td = s_mu[3 + i]
                       - (sR[i][0] * mu_s0 + sR[i][1] * mu_s1 + sR[i][2] * mu_s2);
#pragma unroll
        for (int j = 0; j < 3; j++)
            g_P[b][i * 3 + j] = sR[i][j] * rev[j];   // fold REVERT into columns
        g_P[b][9 + i] = td;
    }
}

// ---------------------------------------------------------------------------
// Kernel 2: streaming apply, batch-inner loop.
// Each thread owns one pixel-quad; mean for that quad lives in registers and
// is reused for BPG batches. Output stored with .cs (evict-first) so the
// write stream does not evict Offset from L2 (Off+mean fit in 126MB L2).
// ---------------------------------------------------------------------------
#define TPB    128
#define BPG    16                 // batches per block group
#define NGRP   (BATCH / BPG)      // 4

__global__ void __launch_bounds__(TPB)
apply_kernel(const float4* __restrict__ Off,
             const float4* __restrict__ mean,
             float4* __restrict__ out)
{
    const int p  = blockIdx.x * TPB + threadIdx.x;   // pixel-quad index
    const int bg = blockIdx.y * BPG;                 // first batch of group

    __shared__ float P[BPG][12];
    for (int i = threadIdx.x; i < BPG * 12; i += TPB)
        (&P[0][0])[i] = g_P[bg + i / 12][i % 12];
    __syncthreads();

    const float4 m0 = __ldg(&mean[p]);
    const float4 m1 = __ldg(&mean[HW4 + p]);
    const float4 m2 = __ldg(&mean[2 * HW4 + p]);

#pragma unroll 4
    for (int bi = 0; bi < BPG; bi++) {
        const size_t base = (size_t)(bg + bi) * 3 * HW4;
        const float4 x0 = __ldg(&Off[base + p]);
        const float4 x1 = __ldg(&Off[base + HW4 + p]);
        const float4 x2 = __ldg(&Off[base + 2 * HW4 + p]);

        const float q0 = P[bi][0], q1 = P[bi][1], q2 = P[bi][2];
        const float q3 = P[bi][3], q4 = P[bi][4], q5 = P[bi][5];
        const float q6 = P[bi][6], q7 = P[bi][7], q8 = P[bi][8];
        const float t0 = P[bi][9], t1 = P[bi][10], t2 = P[bi][11];

        float4 y0, y1, y2;
#define DO_LANE(L)                                            \
    {                                                         \
        const float o0 = fmaf(x0.L, 4.0f, m0.L);              \
        const float o1 = fmaf(x1.L, 4.0f, m1.L);              \
        const float o2 = fmaf(x2.L, 4.0f, m2.L);              \
        y0.L = fmaf(q0, o0, fmaf(q1, o1, fmaf(q2, o2, t0)));  \
        y1.L = fmaf(q3, o0, fmaf(q4, o1, fmaf(q5, o2, t1)));  \
        y2.L = fmaf(q6, o0, fmaf(q7, o1, fmaf(q8, o2, t2)));  \
    }
        DO_LANE(x) DO_LANE(y) DO_LANE(z) DO_LANE(w)
#undef DO_LANE

        __stcs(&out[base + p],           y0);
        __stcs(&out[base + HW4 + p],     y1);
        __stcs(&out[base + 2 * HW4 + p], y2);
    }
}

// ---------------------------------------------------------------------------
extern "C" void kernel_launch(void* const* d_in, const int* in_sizes, int n_in,
                              void* d_out, int out_size)
{
    const float* Off  = (const float*)d_in[0];   // [64,3,256,256]
    const float* Pos  = (const float*)d_in[1];   // [64,3,256,256]
    const float* mean = (const float*)d_in[2];   // [3,256,256]
    const int*   uv   = (const int*)d_in[3];     // [68,2] int32

    float* out = (float*)d_out;                  // [64,3,256,256]

    umeyama_kernel<<<BATCH, 96>>>(Off, Pos, mean, uv);

    dim3 grid(HW4 / TPB, NGRP);                  // (128, 4) = 512 blocks
    apply_kernel<<<grid, TPB>>>((const float4*)Off,
                                (const float4*)mean,
                                (float4*)out);
}

// round 5
// speedup vs baseline: 1.4087x; 1.0374x over previous
#include <cuda_runtime.h>
#include <cstdint>

// Problem constants (fixed shapes from setup_inputs)
#define BATCH 64
#define HDIM  256
#define WDIM  256
#define HW    (HDIM * WDIM)       // 65536
#define HW4   (HW / 4)            // 16384 float4 groups per channel-plane
#define NK    68                  // keypoints

// Per-batch parameters: M[3][3] (sR with REVERT folded into columns) + t[3]
__device__ float g_P[BATCH][12];

// ---------------------------------------------------------------------------
// Kernel 1: per-batch Umeyama similarity estimate (68 points, 3D)
// ---------------------------------------------------------------------------
__global__ void umeyama_kernel(const float* __restrict__ Off,
                               const float* __restrict__ Pos,
                               const float* __restrict__ mean,
                               const int* __restrict__ uv)
{
    const int b = blockIdx.x;
    const int t = threadIdx.x;

    __shared__ float s_src[NK][3];
    __shared__ float s_dst[NK][3];
    __shared__ float s_mu[6];     // mu_s[0..2], mu_d[3..5]
    __shared__ float s_A[9];      // A[i][j] = sum dd_i * sd_j   (no /n)
    __shared__ float s_var;       // sum |sd|^2                  (no /n)

    if (t < NK) {
        const int h = uv[2 * t];
        const int w = uv[2 * t + 1];
        const int pix = h * WDIM + w;
        const float rev[3] = {1.0f, -1.0f, 1.0f};
        const size_t base = (size_t)b * 3 * HW;
#pragma unroll
        for (int c = 0; c < 3; c++) {
            float o = Off[base + (size_t)c * HW + pix];
            float m = mean[(size_t)c * HW + pix];
            s_src[t][c] = fmaf(o, 4.0f, m) * rev[c];
            s_dst[t][c] = Pos[base + (size_t)c * HW + pix];
        }
    }
    __syncthreads();

    if (t < 6) {
        const int c = t % 3;
        float s = 0.0f;
        if (t < 3) { for (int k = 0; k < NK; k++) s += s_src[k][c]; }
        else       { for (int k = 0; k < NK; k++) s += s_dst[k][c]; }
        s_mu[t] = s / (float)NK;
    }
    __syncthreads();

    if (t < 9) {
        const int i = t / 3, j = t % 3;
        const float mdi = s_mu[3 + i];
        const float msj = s_mu[j];
        float s = 0.0f;
        for (int k = 0; k < NK; k++)
            s += (s_dst[k][i] - mdi) * (s_src[k][j] - msj);
        s_A[t] = s;
    } else if (t == 9) {
        float s = 0.0f;
        for (int k = 0; k < NK; k++) {
#pragma unroll
            for (int c = 0; c < 3; c++) {
                float d = s_src[k][c] - s_mu[c];
                s = fmaf(d, d, s);
            }
        }
        s_var = s;
    }
    __syncthreads();

    if (t != 0) return;

    // ---- fast fp32 closed solve on one thread ----
    float A[3][3];
#pragma unroll
    for (int i = 0; i < 3; i++)
#pragma unroll
        for (int j = 0; j < 3; j++) A[i][j] = s_A[i * 3 + j];

    const float detA =
          A[0][0] * (A[1][1] * A[2][2] - A[1][2] * A[2][1])
        - A[0][1] * (A[1][0] * A[2][2] - A[1][2] * A[2][0])
        + A[0][2] * (A[1][0] * A[2][1] - A[1][1] * A[2][0]);

    float Bm[3][3];
#pragma unroll
    for (int i = 0; i < 3; i++)
#pragma unroll
        for (int j = 0; j < 3; j++) {
            float s = 0.0f;
#pragma unroll
            for (int k = 0; k < 3; k++) s = fmaf(A[k][i], A[k][j], s);
            Bm[i][j] = s;
        }

    // Cyclic Jacobi (fp32, exact 2x2 update w/ residual off-diagonal)
    float V[3][3] = {{1,0,0},{0,1,0},{0,0,1}};
    for (int sweep = 0; sweep < 5; sweep++) {
#pragma unroll
        for (int pq = 0; pq < 3; pq++) {
            const int p = (pq == 2) ? 1 : 0;
            const int q = (pq == 0) ? 1 : 2;
            const float apq = Bm[p][q];
            const float app = Bm[p][p], aqq = Bm[q][q];
            if (fabsf(apq) <= 1e-10f * (fabsf(app) + fabsf(aqq))) continue;
            const float theta = __fdividef(aqq - app, 2.0f * apq);
            const float sgn = (theta >= 0.0f) ? 1.0f : -1.0f;
            const float tt = __fdividef(sgn, fabsf(theta) + sqrtf(fmaf(theta, theta, 1.0f)));
            const float c  = rsqrtf(fmaf(tt, tt, 1.0f));
            const float s  = tt * c;
            const float c2 = c * c, s2 = s * s, cs = c * s;
            Bm[p][p] = c2 * app - 2.0f * cs * apq + s2 * aqq;
            Bm[q][q] = s2 * app + 2.0f * cs * apq + c2 * aqq;
            const float res = cs * (app - aqq) + (c2 - s2) * apq;
            Bm[p][q] = Bm[q][p] = res;
            const int k = 3 - p - q;
            const float akp = Bm[k][p], akq = Bm[k][q];
            Bm[k][p] = Bm[p][k] = c * akp - s * akq;
            Bm[k][q] = Bm[q][k] = s * akp + c * akq;
#pragma unroll
            for (int r = 0; r < 3; r++) {
                const float vrp = V[r][p], vrq = V[r][q];
                V[r][p] = c * vrp - s * vrq;
                V[r][q] = s * vrp + c * vrq;
            }
        }
    }

    float wv[3] = {Bm[0][0], Bm[1][1], Bm[2][2]};
    int idx[3] = {0, 1, 2};
#pragma unroll
    for (int i = 0; i < 2; i++)
#pragma unroll
        for (int j = i + 1; j < 3; j++)
            if (wv[idx[j]] > wv[idx[i]]) { int tmp = idx[i]; idx[i] = idx[j]; idx[j] = tmp; }

    float S[3], U[3][3], Vs[3][3];
#pragma unroll
    for (int c2 = 0; c2 < 3; c2++) {
        const int ic = idx[c2];
        const float sv = sqrtf(fmaxf(wv[ic], 0.0f));
        S[c2] = sv;
        const float inv = (sv > 0.0f) ? __fdividef(1.0f, sv) : 0.0f;
#pragma unroll
        for (int r = 0; r < 3; r++) Vs[r][c2] = V[r][ic];
#pragma unroll
        for (int r = 0; r < 3; r++) {
            float s = 0.0f;
#pragma unroll
            for (int k = 0; k < 3; k++) s = fmaf(A[r][k], Vs[k][c2], s);
            U[r][c2] = s * inv;
        }
    }

    const float d3 = (detA < 0.0f) ? -1.0f : 1.0f;
    const float scale = __fdividef(S[0] + S[1] + d3 * S[2], s_var);

    float sR[3][3];
#pragma unroll
    for (int i = 0; i < 3; i++)
#pragma unroll
        for (int j = 0; j < 3; j++) {
            const float r = U[i][0] * Vs[j][0] + U[i][1] * Vs[j][1]
                          + d3 * U[i][2] * Vs[j][2];
            sR[i][j] = scale * r;
        }

    const float rev[3] = {1.0f, -1.0f, 1.0f};
    const float mu_s0 = s_mu[0], mu_s1 = s_mu[1], mu_s2 = s_mu[2];
#pragma unroll
    for (int i = 0; i < 3; i++) {
        const float td = s_mu[3 + i]
                       - (sR[i][0] * mu_s0 + sR[i][1] * mu_s1 + sR[i][2] * mu_s2);
#pragma unroll
        for (int j = 0; j < 3; j++)
            g_P[b][i * 3 + j] = sR[i][j] * rev[j];   // fold REVERT into columns
        g_P[b][9 + i] = td;
    }
}

// ---------------------------------------------------------------------------
// Kernel 2: streaming apply, batch-inner loop over a SMALL batch group (4)
// to keep thread-level parallelism high (262K threads) while still reusing
// mean from registers 4x. Off/mean via __ldg (L2-resident across replays);
// out via __stcs (evict-first, protects L2).
// ---------------------------------------------------------------------------
#define TPB    256
#define BPG    4                  // batches per block group
#define NGRP   (BATCH / BPG)      // 16

__global__ void __launch_bounds__(TPB)
apply_kernel(const float4* __restrict__ Off,
             const float4* __restrict__ mean,
             float4* __restrict__ out)
{
    const int p  = blockIdx.x * TPB + threadIdx.x;   // pixel-quad index
    const int bg = blockIdx.y * BPG;                 // first batch of group

    __shared__ float P[BPG][12];
    if (threadIdx.x < BPG * 12)
        (&P[0][0])[threadIdx.x] = g_P[bg + threadIdx.x / 12][threadIdx.x % 12];
    __syncthreads();

    const float4 m0 = __ldg(&mean[p]);
    const float4 m1 = __ldg(&mean[HW4 + p]);
    const float4 m2 = __ldg(&mean[2 * HW4 + p]);

#pragma unroll
    for (int bi = 0; bi < BPG; bi++) {
        const size_t base = (size_t)(bg + bi) * 3 * HW4;
        const float4 x0 = __ldg(&Off[base + p]);
        const float4 x1 = __ldg(&Off[base + HW4 + p]);
        const float4 x2 = __ldg(&Off[base + 2 * HW4 + p]);

        const float q0 = P[bi][0], q1 = P[bi][1], q2 = P[bi][2];
        const float q3 = P[bi][3], q4 = P[bi][4], q5 = P[bi][5];
        const float q6 = P[bi][6], q7 = P[bi][7], q8 = P[bi][8];
        const float t0 = P[bi][9], t1 = P[bi][10], t2 = P[bi][11];

        float4 y0, y1, y2;
#define DO_LANE(L)                                            \
    {                                                         \
        const float o0 = fmaf(x0.L, 4.0f, m0.L);              \
        const float o1 = fmaf(x1.L, 4.0f, m1.L);              \
        const float o2 = fmaf(x2.L, 4.0f, m2.L);              \
        y0.L = fmaf(q0, o0, fmaf(q1, o1, fmaf(q2, o2, t0)));  \
        y1.L = fmaf(q3, o0, fmaf(q4, o1, fmaf(q5, o2, t1)));  \
        y2.L = fmaf(q6, o0, fmaf(q7, o1, fmaf(q8, o2, t2)));  \
    }
        DO_LANE(x) DO_LANE(y) DO_LANE(z) DO_LANE(w)
#undef DO_LANE

        __stcs(&out[base + p],           y0);
        __stcs(&out[base + HW4 + p],     y1);
        __stcs(&out[base + 2 * HW4 + p], y2);
    }
}

// ---------------------------------------------------------------------------
extern "C" void kernel_launch(void* const* d_in, const int* in_sizes, int n_in,
                              void* d_out, int out_size)
{
    const float* Off  = (const float*)d_in[0];   // [64,3,256,256]
    const float* Pos  = (const float*)d_in[1];   // [64,3,256,256]
    const float* mean = (const float*)d_in[2];   // [3,256,256]
    const int*   uv   = (const int*)d_in[3];     // [68,2] int32

    float* out = (float*)d_out;                  // [64,3,256,256]

    umeyama_kernel<<<BATCH, 96>>>(Off, Pos, mean, uv);

    dim3 grid(HW4 / TPB, NGRP);                  // (64, 16) = 1024 blocks
    apply_kernel<<<grid, TPB>>>((const float4*)Off,
                                (const float4*)mean,
                                (float4*)out);
}